// round 2
// baseline (speedup 1.0000x reference)
#include <cuda_runtime.h>
#include <cstdint>

#define N_NODES 100000
#define D 64
#define N_EDGES 1600000
#define VEC_PER_ROW (D / 4)   // 16 float4 per node row

// Scratch: per-node in-degree counts (self-loop pre-seeded to 1.0).
__device__ float g_counts[N_NODES];

// 16-byte vector reduction to global memory (no return) — sm_90+.
__device__ __forceinline__ void red_add_v4(float* p, float4 v) {
    asm volatile("red.global.add.v4.f32 [%0], {%1, %2, %3, %4};"
                 :: "l"(p), "f"(v.x), "f"(v.y), "f"(v.z), "f"(v.w)
                 : "memory");
}

// Kernel 1: out_real = Z_real, out_imag = Z_imag (self-loop contribution),
// counts = 1.0 (self-loop + clamp-to->=1 handled simultaneously).
__global__ void init_kernel(const float* __restrict__ Zr,
                            const float* __restrict__ Zi,
                            float* __restrict__ out) {
    int idx = blockIdx.x * blockDim.x + threadIdx.x;
    const int total_vec = N_NODES * VEC_PER_ROW;  // 1.6M float4s per array
    if (idx < total_vec) {
        const float4* zr = (const float4*)Zr;
        const float4* zi = (const float4*)Zi;
        float4* o_r = (float4*)out;
        float4* o_i = (float4*)(out + (size_t)N_NODES * D);
        o_r[idx] = zr[idx];
        o_i[idx] = zi[idx];
    }
    if (idx < N_NODES) {
        g_counts[idx] = 1.0f;
    }
}

// Kernel 2: per edge, gather Z[src] and vector-reduce into out[dst].
// 16 threads per edge: each thread handles one float4 of real + one of imag.
// Edge indices are int32 (JAX default x64-disabled downgrades int64 -> int32).
__global__ void edge_kernel(const float* __restrict__ Zr,
                            const float* __restrict__ Zi,
                            const int* __restrict__ ei,
                            float* __restrict__ out) {
    long long t = (long long)blockIdx.x * blockDim.x + threadIdx.x;
    long long e = t >> 4;
    int lane = (int)(t & 15);
    if (e >= N_EDGES) return;

    int src = ei[e];
    int dst = ei[N_EDGES + e];
    // Defensive: if dtype assumption is wrong, fail via rel_err, not a crash.
    if ((unsigned)src >= N_NODES || (unsigned)dst >= N_NODES) return;

    const float4* zr = (const float4*)(Zr + (size_t)src * D);
    const float4* zi = (const float4*)(Zi + (size_t)src * D);
    float4 vr = zr[lane];
    float4 vi = zi[lane];

    float* o_r = out + (size_t)dst * D + lane * 4;
    float* o_i = out + (size_t)N_NODES * D + (size_t)dst * D + lane * 4;
    red_add_v4(o_r, vr);
    red_add_v4(o_i, vi);

    if (lane == 0) {
        atomicAdd(&g_counts[dst], 1.0f);
    }
}

// Kernel 3: normalize each node row by 1/count.
__global__ void norm_kernel(float* __restrict__ out) {
    int idx = blockIdx.x * blockDim.x + threadIdx.x;  // one float4 (both arrays)
    const int total_vec = N_NODES * VEC_PER_ROW;
    if (idx >= total_vec) return;

    int n = idx >> 4;  // node id
    float inv = 1.0f / g_counts[n];

    float4* o_r = (float4*)out;
    float4* o_i = (float4*)(out + (size_t)N_NODES * D);

    float4 v = o_r[idx];
    v.x *= inv; v.y *= inv; v.z *= inv; v.w *= inv;
    o_r[idx] = v;

    v = o_i[idx];
    v.x *= inv; v.y *= inv; v.z *= inv; v.w *= inv;
    o_i[idx] = v;
}

extern "C" void kernel_launch(void* const* d_in, const int* in_sizes, int n_in,
                              void* d_out, int out_size) {
    const float* Zr = (const float*)d_in[0];
    const float* Zi = (const float*)d_in[1];
    const int* ei = (const int*)d_in[2];
    float* out = (float*)d_out;

    {
        const int total_vec = N_NODES * VEC_PER_ROW;  // 1,600,000
        int threads = 256;
        int blocks = (total_vec + threads - 1) / threads;
        init_kernel<<<blocks, threads>>>(Zr, Zi, out);
    }
    {
        long long total_threads = (long long)N_EDGES * 16;  // 25.6M
        int threads = 256;
        long long blocks = (total_threads + threads - 1) / threads;
        edge_kernel<<<(unsigned)blocks, threads>>>(Zr, Zi, ei, out);
    }
    {
        const int total_vec = N_NODES * VEC_PER_ROW;
        int threads = 256;
        int blocks = (total_vec + threads - 1) / threads;
        norm_kernel<<<blocks, threads>>>(out);
    }
}

// round 3
// speedup vs baseline: 1.5292x; 1.5292x over previous
#include <cuda_runtime.h>
#include <cstdint>

#define N_NODES 100000
#define D 64
#define VEC_PER_ROW (D / 4)      // 16 float4 per node row
#define N_EDGES 1600000

#define SCAN_CHUNK 512
#define N_SCAN_BLOCKS ((N_NODES + SCAN_CHUNK - 1) / SCAN_CHUNK)   // 196

// Static scratch (allocation-free rule).
__device__ int g_counts[N_NODES];      // in-degree (excluding self-loop)
__device__ int g_row_start[N_NODES];   // CSR offsets
__device__ int g_cursor[N_NODES];      // fill cursors
__device__ int g_block_sums[N_SCAN_BLOCKS];
__device__ int g_block_offs[N_SCAN_BLOCKS];
__device__ int g_csr_src[N_EDGES];     // src ids grouped by dst

// ---------------------------------------------------------------- CSR build
__global__ void zero_counts_kernel() {
    int i = blockIdx.x * blockDim.x + threadIdx.x;
    if (i < N_NODES) g_counts[i] = 0;
}

__global__ void count_kernel(const int* __restrict__ ei) {
    int e = blockIdx.x * blockDim.x + threadIdx.x;
    if (e < N_EDGES) {
        int dst = ei[N_EDGES + e];
        atomicAdd(&g_counts[dst], 1);
    }
}

// Per-chunk sums (512 elements per block).
__global__ void scan1_kernel() {
    __shared__ int sdata[SCAN_CHUNK];
    int tid = threadIdx.x;
    int i = blockIdx.x * SCAN_CHUNK + tid;
    sdata[tid] = (i < N_NODES) ? g_counts[i] : 0;
    __syncthreads();
    for (int s = SCAN_CHUNK / 2; s > 0; s >>= 1) {
        if (tid < s) sdata[tid] += sdata[tid + s];
        __syncthreads();
    }
    if (tid == 0) g_block_sums[blockIdx.x] = sdata[0];
}

// Serial exclusive scan of chunk sums (196 elements — trivial).
__global__ void scan2_kernel() {
    if (threadIdx.x == 0 && blockIdx.x == 0) {
        int acc = 0;
        for (int b = 0; b < N_SCAN_BLOCKS; b++) {
            g_block_offs[b] = acc;
            acc += g_block_sums[b];
        }
    }
}

// In-chunk exclusive scan + chunk offset -> row_start, cursor.
__global__ void scan3_kernel() {
    __shared__ int sdata[SCAN_CHUNK];
    int tid = threadIdx.x;
    int i = blockIdx.x * SCAN_CHUNK + tid;
    int v = (i < N_NODES) ? g_counts[i] : 0;
    sdata[tid] = v;
    __syncthreads();
    // Hillis-Steele inclusive scan.
    for (int off = 1; off < SCAN_CHUNK; off <<= 1) {
        int t = (tid >= off) ? sdata[tid - off] : 0;
        __syncthreads();
        sdata[tid] += t;
        __syncthreads();
    }
    if (i < N_NODES) {
        int excl = sdata[tid] - v + g_block_offs[blockIdx.x];
        g_row_start[i] = excl;
        g_cursor[i] = excl;
    }
}

__global__ void fill_kernel(const int* __restrict__ ei) {
    int e = blockIdx.x * blockDim.x + threadIdx.x;
    if (e < N_EDGES) {
        int src = ei[e];
        int dst = ei[N_EDGES + e];
        int pos = atomicAdd(&g_cursor[dst], 1);
        g_csr_src[pos] = src;
    }
}

// ---------------------------------------------------------------- aggregate
// One warp per destination node. Lane c<16 handles float4 chunk c of the real
// row; lane c>=16 handles chunk c-16 of the imag row. Accumulator starts with
// the node's own row (self-loop); final scale 1/(deg+1) gives the mean.
__global__ void aggregate_kernel(const float* __restrict__ Zr,
                                 const float* __restrict__ Zi,
                                 float* __restrict__ out) {
    int warp_id = (blockIdx.x * blockDim.x + threadIdx.x) >> 5;
    int lane = threadIdx.x & 31;
    if (warp_id >= N_NODES) return;
    int n = warp_id;

    const float4* Zr4 = (const float4*)Zr;
    const float4* Zi4 = (const float4*)Zi;

    bool is_real = lane < 16;
    int chunk = is_real ? lane : lane - 16;

    // self-loop init
    float4 acc = is_real ? Zr4[(size_t)n * VEC_PER_ROW + chunk]
                         : Zi4[(size_t)n * VEC_PER_ROW + chunk];

    int start = g_row_start[n];
    int deg = g_counts[n];

    // software-pipelined index to overlap index load with gather
    int s_next = (deg > 0) ? g_csr_src[start] : 0;
    for (int j = 0; j < deg; j++) {
        int s = s_next;
        if (j + 1 < deg) s_next = g_csr_src[start + j + 1];
        float4 v = is_real ? Zr4[(size_t)s * VEC_PER_ROW + chunk]
                           : Zi4[(size_t)s * VEC_PER_ROW + chunk];
        acc.x += v.x; acc.y += v.y; acc.z += v.z; acc.w += v.w;
    }

    float inv = 1.0f / (float)(deg + 1);
    acc.x *= inv; acc.y *= inv; acc.z *= inv; acc.w *= inv;

    float4* o = is_real ? (float4*)out : (float4*)(out + (size_t)N_NODES * D);
    o[(size_t)n * VEC_PER_ROW + chunk] = acc;
}

// ---------------------------------------------------------------- launch
extern "C" void kernel_launch(void* const* d_in, const int* in_sizes, int n_in,
                              void* d_out, int out_size) {
    const float* Zr = (const float*)d_in[0];
    const float* Zi = (const float*)d_in[1];
    const int* ei = (const int*)d_in[2];
    float* out = (float*)d_out;

    {
        int threads = 256;
        int blocks = (N_NODES + threads - 1) / threads;
        zero_counts_kernel<<<blocks, threads>>>();
    }
    {
        int threads = 256;
        int blocks = (N_EDGES + threads - 1) / threads;
        count_kernel<<<blocks, threads>>>(ei);
    }
    scan1_kernel<<<N_SCAN_BLOCKS, SCAN_CHUNK>>>();
    scan2_kernel<<<1, 32>>>();
    scan3_kernel<<<N_SCAN_BLOCKS, SCAN_CHUNK>>>();
    {
        int threads = 256;
        int blocks = (N_EDGES + threads - 1) / threads;
        fill_kernel<<<blocks, threads>>>(ei);
    }
    {
        // one warp per node: 100000 warps, 8 warps (256 threads) per block
        int threads = 256;
        int blocks = (N_NODES * 32 + threads - 1) / threads;  // 12500
        aggregate_kernel<<<blocks, threads>>>(Zr, Zi, out);
    }
}